// round 3
// baseline (speedup 1.0000x reference)
#include <cuda_runtime.h>

// ---------------------------------------------------------------------------
// RNN_57208964382771: Elman RNN (tanh), B=64, T=2048, H=8, V=O=1000
//   Phase 0: detect whether X/lengths arrived as int64 or int32.
//   Phase 1 (64 blocks): per-sequence recurrence.
//     - embproj[v][i] = emb[v]·W_ih[i] + b_ih[i] + b_hh[i]  (SMEM, per block)
//     - warp 0: lane i owns h[i]; step = dot8 + tanhf + shfl broadcast
//   Phase 2: logits[row,o] = hs[row]·W_out[o] + b_out[o]  (store-bound, 524MB)
// ---------------------------------------------------------------------------

#define HH 8
#define MAX_B 64
#define MAX_T 2048

__device__ float g_hs[(size_t)MAX_B * MAX_T * HH];  // masked hidden states
__device__ int   g_is64;                            // 1 if X/lengths are int64

// --- Phase 0: dtype detection -------------------------------------------------
// If X is int64 (values < 2^31, non-negative), every odd int32 word is zero.
__global__ void detect_dtype_kernel(const int* __restrict__ x32, int n)
{
    int nz = 0;
    const int pairs = n >> 1;
    for (int i = threadIdx.x; i < pairs; i += blockDim.x)
        nz |= (x32[2 * i + 1] != 0);
    if (__syncthreads_or(nz)) { if (threadIdx.x == 0) g_is64 = 0; }
    else                      { if (threadIdx.x == 0) g_is64 = 1; }
}

// --- Phase 1: recurrence ------------------------------------------------------
__global__ void rnn_recur_kernel(const void* __restrict__ Xv,
                                 const void* __restrict__ lengthsv,
                                 const float* __restrict__ emb,
                                 const float* __restrict__ W_ih,
                                 const float* __restrict__ W_hh,
                                 const float* __restrict__ b_ih,
                                 const float* __restrict__ b_hh,
                                 int T, int V)
{
    __shared__ float s_embproj[1000 * HH];   // 32 KB
    __shared__ int   s_tok[MAX_T + 2];       // 8 KB

    const int b    = blockIdx.x;
    const int tid  = threadIdx.x;
    const int is64 = g_is64;

    // --- load tokens (either dtype -> int32), clamped to [0, V) ---
    if (is64) {
        const long long* X = (const long long*)Xv;
        for (int t = tid; t < T; t += blockDim.x) {
            int v = (int)X[(long long)b * T + t];
            s_tok[t] = min(max(v, 0), V - 1);
        }
    } else {
        const int* X = (const int*)Xv;
        for (int t = tid; t < T; t += blockDim.x) {
            int v = X[b * T + t];
            s_tok[t] = min(max(v, 0), V - 1);
        }
    }
    if (tid < 2) s_tok[T + tid] = 0;

    // --- embedding projection with both biases folded in ---
    for (int v = tid; v < V; v += blockDim.x) {
        float e[HH];
#pragma unroll
        for (int h = 0; h < HH; h++) e[h] = emb[v * HH + h];
#pragma unroll
        for (int i = 0; i < HH; i++) {
            float s = b_ih[i] + b_hh[i];
#pragma unroll
            for (int h = 0; h < HH; h++)
                s = fmaf(e[h], W_ih[i * HH + h], s);
            s_embproj[v * HH + i] = s;
        }
    }
    __syncthreads();

    if (tid >= 32) return;   // recurrence: warp 0 only
    const int lane = tid;
    const int i    = lane & 7;     // lanes 8-31 shadow lanes 0-7 (full-mask shfl)

    float w[HH];
#pragma unroll
    for (int j = 0; j < HH; j++) w[j] = W_hh[i * HH + j];

    long long len;
    if (is64) len = ((const long long*)lengthsv)[b];
    else      len = (long long)((const int*)lengthsv)[b];

    float hr[HH];
#pragma unroll
    for (int j = 0; j < HH; j++) hr[j] = 0.0f;

    float* __restrict__ hs_out = g_hs + (size_t)b * T * HH;

    // software-pipelined xp prefetch (token at +2, xp at +1)
    int   tokB = s_tok[1];
    float xp   = s_embproj[s_tok[0] * HH + i];

    for (int t = 0; t < T; t++) {
        const int   tokC = s_tok[t + 2];
        const float xp_n = s_embproj[tokB * HH + i];

        // dot(h, W_hh row i) + xp  — balanced tree for short latency
        float p0 = fmaf(hr[0], w[0], xp);
        float p1 = hr[1] * w[1];
        float p2 = hr[2] * w[2];
        float p3 = hr[3] * w[3];
        float p4 = hr[4] * w[4];
        float p5 = hr[5] * w[5];
        float p6 = hr[6] * w[6];
        float p7 = hr[7] * w[7];
        float s  = ((p0 + p1) + (p2 + p3)) + ((p4 + p5) + (p6 + p7));

        float y = tanhf(s);

        float ov = (t < (int)len) ? y : 0.0f;
        if (lane < HH) hs_out[t * HH + lane] = ov;

#pragma unroll
        for (int j = 0; j < HH; j++)
            hr[j] = __shfl_sync(0xffffffffu, y, j);

        xp   = xp_n;
        tokB = tokC;
    }
}

// --- Phase 2: output projection, store-bound ---------------------------------
#define ROWS_PER_BLOCK 64

__global__ void rnn_proj_kernel(const float* __restrict__ W_out,
                                const float* __restrict__ b_out,
                                const void* __restrict__ lengthsv,
                                float* __restrict__ out,
                                int B, int O, int totalRows, int tail)
{
    const int tid  = threadIdx.x;
    const int nvec = O >> 2;               // 250 float4 per row

    float w[4][HH];
    float4 bias = make_float4(0.f, 0.f, 0.f, 0.f);
    if (tid < nvec) {
#pragma unroll
        for (int k = 0; k < 4; k++) {
            const int o = tid * 4 + k;
#pragma unroll
            for (int h = 0; h < HH; h++)
                w[k][h] = W_out[o * HH + h];
        }
        bias = *(const float4*)(b_out + tid * 4);
    }

    const long long row0 = (long long)blockIdx.x * ROWS_PER_BLOCK;

#pragma unroll 2
    for (int r = 0; r < ROWS_PER_BLOCK; r++) {
        const long long row = row0 + r;
        if (row >= totalRows) break;

        const float4* hp = (const float4*)(g_hs + (size_t)row * HH);
        const float4 ha = __ldg(hp);
        const float4 hb = __ldg(hp + 1);
        const float hh[HH] = {ha.x, ha.y, ha.z, ha.w, hb.x, hb.y, hb.z, hb.w};

        if (tid < nvec) {
            float a0 = bias.x, a1 = bias.y, a2 = bias.z, a3 = bias.w;
#pragma unroll
            for (int h = 0; h < HH; h++) {
                a0 = fmaf(w[0][h], hh[h], a0);
                a1 = fmaf(w[1][h], hh[h], a1);
                a2 = fmaf(w[2][h], hh[h], a2);
                a3 = fmaf(w[3][h], hh[h], a3);
            }
            float4 acc; acc.x = a0; acc.y = a1; acc.z = a2; acc.w = a3;
            *(float4*)(out + row * O + tid * 4) = acc;
        }
    }

    // tail: lengths output (tuple second element), layout inferred from size
    if (blockIdx.x == 0 && tail > 0) {
        const int is64 = g_is64;
        const long long base = (long long)totalRows * O;
        long long lv = 0;
        if (tid < B)
            lv = is64 ? ((const long long*)lengthsv)[tid]
                      : (long long)((const int*)lengthsv)[tid];

        if (tail == 2 * B) {
            // raw int64 bit-pattern occupying 2 fp32 slots each
            if (tid < B) ((long long*)(out + base))[tid] = lv;
        } else {
            for (int k = tid; k < tail; k += blockDim.x) {
                float v = 0.0f;
                if (k < B)
                    v = (float)(is64 ? ((const long long*)lengthsv)[k]
                                     : (long long)((const int*)lengthsv)[k]);
                out[base + k] = v;
            }
        }
    }
}

extern "C" void kernel_launch(void* const* d_in, const int* in_sizes, int n_in,
                              void* d_out, int out_size)
{
    const void*  X       = d_in[0];
    const void*  lengths = d_in[1];
    const float* emb     = (const float*)d_in[2];
    const float* W_ih    = (const float*)d_in[3];
    const float* W_hh    = (const float*)d_in[4];
    const float* b_ih    = (const float*)d_in[5];
    const float* b_hh    = (const float*)d_in[6];
    const float* W_out   = (const float*)d_in[7];
    const float* b_out   = (const float*)d_in[8];
    float*       out     = (float*)d_out;

    const int B  = in_sizes[1];
    const int BT = in_sizes[0];
    const int T  = BT / B;
    const int H  = in_sizes[5];          // 8
    const int V  = in_sizes[2] / H;
    const int O  = in_sizes[8];

    const long long tail = (long long)out_size - (long long)BT * O;

    detect_dtype_kernel<<<1, 256>>>((const int*)X, BT);

    rnn_recur_kernel<<<B, 256>>>(X, lengths, emb, W_ih, W_hh, b_ih, b_hh, T, V);

    const int nblk = (BT + ROWS_PER_BLOCK - 1) / ROWS_PER_BLOCK;
    // NOTE: argument order matches (B, O, totalRows, tail) — R2 bug was a swap here.
    rnn_proj_kernel<<<nblk, 256>>>(W_out, b_out, lengths, out,
                                   B, O, BT, (int)(tail > 0 ? tail : 0));
}

// round 4
// speedup vs baseline: 1.5342x; 1.5342x over previous
#include <cuda_runtime.h>

// ---------------------------------------------------------------------------
// RNN_57208964382771: Elman RNN (tanh), B=64, T=2048, H=8, V=O=1000
// Fused persistent kernel, single wave:
//   blocks [0, B)          : recurrence role (one sequence each)
//     - inline int64/int32 dtype detect on X (first 1024 pairs)
//     - embproj[v][i] = emb[v]·W_ih[i] + b_ih + b_hh   (SMEM)
//     - warp 0: lane i owns h[i]; step = dot8 + tanh.approx + shfl
//     - every CH=128 steps: threadfence + progress[b] = chunk+1
//   blocks [B, B+NPROJ)    : projection role (work list of (chunk,batch) tiles)
//     - spin on progress[b] > c, then logits rows of that tile (store-bound)
// Overlap: projection of chunk c runs while recurrence computes chunk c+1.
// All 212 blocks are co-resident (smem 40KB -> 5 blocks/SM) => no deadlock.
// ---------------------------------------------------------------------------

#define HH     8
#define MAX_B  64
#define MAX_T  2048
#define MAX_V  1000
#define CH     128          // timesteps per chunk / rows per proj tile
#define NPROJ  148          // projection blocks (one per SM)

__device__ float g_hs[(size_t)MAX_B * MAX_T * HH];  // masked hidden states
__device__ int   g_progress[MAX_B];                 // chunks completed per batch (memset 0 pre-launch)

__device__ __forceinline__ float fast_tanh(float x)
{
    float y;
    asm("tanh.approx.f32 %0, %1;" : "=f"(y) : "f"(x));
    return y;
}

__global__ void __launch_bounds__(256, 2)
rnn_fused_kernel(const void* __restrict__ Xv,
                 const void* __restrict__ lengthsv,
                 const float* __restrict__ emb,
                 const float* __restrict__ W_ih,
                 const float* __restrict__ W_hh,
                 const float* __restrict__ b_ih,
                 const float* __restrict__ b_hh,
                 const float* __restrict__ W_out,
                 const float* __restrict__ b_out,
                 float* __restrict__ out,
                 int B, int T, int V, int O, int tail)
{
    const int bid = blockIdx.x;
    const int tid = threadIdx.x;
    const int nchunk = (T + CH - 1) / CH;

    if (bid < B) {
        // =================== recurrence role ===================
        __shared__ float s_embproj[MAX_V * HH];   // 32 KB
        __shared__ int   s_tok[MAX_T + 2];        // 8 KB
        __shared__ int   s_is64;

        const int b = bid;

        // --- inline dtype detect: int64 tokens (<2^31) have zero odd words ---
        {
            const int* x32 = (const int*)Xv;
            const int pairs = min(1024, (B * T) >> 1);
            int nz = 0;
            for (int i = tid; i < pairs; i += blockDim.x)
                nz |= (x32[2 * i + 1] != 0);
            const int any = __syncthreads_or(nz);
            if (tid == 0) s_is64 = !any;
            __syncthreads();
        }
        const int is64 = s_is64;

        // --- load tokens -> int32, clamped to [0, V) ---
        if (is64) {
            const long long* X = (const long long*)Xv;
            for (int t = tid; t < T; t += blockDim.x) {
                int v = (int)X[(long long)b * T + t];
                s_tok[t] = min(max(v, 0), V - 1);
            }
        } else {
            const int* X = (const int*)Xv;
            for (int t = tid; t < T; t += blockDim.x) {
                int v = X[b * T + t];
                s_tok[t] = min(max(v, 0), V - 1);
            }
        }
        if (tid < 2) s_tok[T + tid] = 0;

        // --- embedding projection with both biases folded in ---
        for (int v = tid; v < V; v += blockDim.x) {
            float e[HH];
#pragma unroll
            for (int h = 0; h < HH; h++) e[h] = emb[v * HH + h];
#pragma unroll
            for (int i = 0; i < HH; i++) {
                float s = b_ih[i] + b_hh[i];
#pragma unroll
                for (int h = 0; h < HH; h++)
                    s = fmaf(e[h], W_ih[i * HH + h], s);
                s_embproj[v * HH + i] = s;
            }
        }
        __syncthreads();

        if (tid >= 32) return;   // recurrence: warp 0 only
        const int lane = tid;
        const int i    = lane & 7;   // lanes 8-31 shadow 0-7 (full-mask shfl)

        float w[HH];
#pragma unroll
        for (int j = 0; j < HH; j++) w[j] = W_hh[i * HH + j];

        long long len;
        if (is64) len = ((const long long*)lengthsv)[b];
        else      len = (long long)((const int*)lengthsv)[b];
        const int ilen = (int)len;

        float hr[HH];
#pragma unroll
        for (int j = 0; j < HH; j++) hr[j] = 0.0f;

        float* __restrict__ hs_out = g_hs + (size_t)b * T * HH;

        int   tokB = s_tok[1];
        float xp   = s_embproj[s_tok[0] * HH + i];

        for (int c = 0; c < nchunk; c++) {
            const int tend = min(T, (c + 1) * CH);
            for (int t = c * CH; t < tend; t++) {
                const int   tokC = s_tok[t + 2];
                const float xp_n = s_embproj[tokB * HH + i];

                float p0 = fmaf(hr[0], w[0], xp);
                float p1 = hr[1] * w[1];
                float p2 = hr[2] * w[2];
                float p3 = hr[3] * w[3];
                float p4 = hr[4] * w[4];
                float p5 = hr[5] * w[5];
                float p6 = hr[6] * w[6];
                float p7 = hr[7] * w[7];
                float s  = ((p0 + p1) + (p2 + p3)) + ((p4 + p5) + (p6 + p7));

                const float y = fast_tanh(s);

                const float ov = (t < ilen) ? y : 0.0f;
                if (lane < HH) hs_out[t * HH + lane] = ov;

#pragma unroll
                for (int j = 0; j < HH; j++)
                    hr[j] = __shfl_sync(0xffffffffu, y, j);

                xp   = xp_n;
                tokB = tokC;
            }
            // publish chunk: whole warp fences (covers all lanes' stores)
            __threadfence();
            if (lane == 0) atomicExch(&g_progress[b], c + 1);
        }
        return;
    }

    // =================== projection role ===================
    const int p = bid - B;             // 0 .. NPROJ-1
    const int nvec = O >> 2;           // 250 float4 per row

    // tail: lengths passthrough (no hs dependency) — block p==0 handles it
    if (p == 0 && tail > 0 && tid < 256) {
        // deterministic dtype detect on lengths: values >= 1, so int32 data has
        // nonzero odd words among the first B words; int64 data has them all 0.
        const int* l32 = (const int*)lengthsv;
        int nz = 0;
        for (int k = 1; k < B; k += 2) nz |= (l32[k] != 0);
        const int is64l = !nz;

        const long long base = (long long)B * T * O;
        if (tail == 2 * B) {
            if (tid < B) {
                long long lv = is64l ? ((const long long*)lengthsv)[tid]
                                     : (long long)l32[tid];
                ((long long*)(out + base))[tid] = lv;
            }
        } else {
            for (int k = tid; k < tail; k += 256) {
                float v = 0.0f;
                if (k < B)
                    v = (float)(is64l ? ((const long long*)lengthsv)[k]
                                      : (long long)l32[k]);
                out[base + k] = v;
            }
        }
    }

    if (tid >= nvec) return;

    // loop-invariant per-thread output weights (4 outputs x 8)
    float w[4][HH];
#pragma unroll
    for (int k = 0; k < 4; k++) {
        const int o = tid * 4 + k;
#pragma unroll
        for (int h = 0; h < HH; h++)
            w[k][h] = W_out[o * HH + h];
    }
    const float4 bias = *(const float4*)(b_out + tid * 4);

    const int ntiles = B * nchunk;
    volatile int* prog = g_progress;

    for (int tile = p; tile < ntiles; tile += NPROJ) {
        const int c = tile / B;        // chunk
        const int b = tile % B;        // batch

        while (prog[b] <= c) __nanosleep(100);
        __threadfence();               // acquire: hs writes visible

        const int t0   = c * CH;
        const int rows = min(CH, T - t0);
        const float* __restrict__ hsrow = g_hs + ((size_t)b * T + t0) * HH;
        float* __restrict__ orow = out + ((size_t)b * T + t0) * O + tid * 4;

        for (int r = 0; r < rows; r++) {
            const float4 ha = __ldg((const float4*)(hsrow + (size_t)r * HH));
            const float4 hb = __ldg((const float4*)(hsrow + (size_t)r * HH) + 1);
            const float hh[HH] = {ha.x, ha.y, ha.z, ha.w, hb.x, hb.y, hb.z, hb.w};

            float a0 = bias.x, a1 = bias.y, a2 = bias.z, a3 = bias.w;
#pragma unroll
            for (int h = 0; h < HH; h++) {
                a0 = fmaf(w[0][h], hh[h], a0);
                a1 = fmaf(w[1][h], hh[h], a1);
                a2 = fmaf(w[2][h], hh[h], a2);
                a3 = fmaf(w[3][h], hh[h], a3);
            }
            float4 acc; acc.x = a0; acc.y = a1; acc.z = a2; acc.w = a3;
            *(float4*)(orow + (size_t)r * O) = acc;
        }
    }
}

extern "C" void kernel_launch(void* const* d_in, const int* in_sizes, int n_in,
                              void* d_out, int out_size)
{
    const void*  X       = d_in[0];
    const void*  lengths = d_in[1];
    const float* emb     = (const float*)d_in[2];
    const float* W_ih    = (const float*)d_in[3];
    const float* W_hh    = (const float*)d_in[4];
    const float* b_ih    = (const float*)d_in[5];
    const float* b_hh    = (const float*)d_in[6];
    const float* W_out   = (const float*)d_in[7];
    const float* b_out   = (const float*)d_in[8];
    float*       out     = (float*)d_out;

    const int B  = in_sizes[1];
    const int BT = in_sizes[0];
    const int T  = BT / B;
    const int H  = in_sizes[5];          // 8
    const int V  = in_sizes[2] / H;
    const int O  = in_sizes[8];

    const long long tail = (long long)out_size - (long long)BT * O;

    // reset progress flags (captured as a memset node; ordered before kernel)
    void* progAddr = nullptr;
    cudaGetSymbolAddress(&progAddr, g_progress);
    cudaMemsetAsync(progAddr, 0, sizeof(int) * MAX_B);

    rnn_fused_kernel<<<B + NPROJ, 256>>>(X, lengths, emb, W_ih, W_hh, b_ih, b_hh,
                                         W_out, b_out, out,
                                         B, T, V, O, (int)(tail > 0 ? tail : 0));
}

// round 5
// speedup vs baseline: 1.9455x; 1.2681x over previous
#include <cuda_runtime.h>

// ---------------------------------------------------------------------------
// RNN_57208964382771: Elman RNN (tanh), B=64, T=2048, H=8, V=O=1000
// Fused persistent kernel, single wave (212 blocks, all co-resident):
//   blocks [0, B)        : recurrence (one sequence each, warp 0)
//       step = 2x4-FFMA chain + tanh.approx + 8x shfl broadcast (UNMASKED)
//       publish per 128-step chunk: __syncwarp + st.release.gpu flag
//   blocks [B, B+NPROJ)  : projection over (chunk,batch) tiles
//       mask applied HERE: rows t >= len[b]  -> out = b_out (no hs dependency,
//       written immediately in phase 1, hidden under the recurrence)
//       rows t < len[b]   -> spin (tid0 only, acquire) then W_out·h + b_out
// ---------------------------------------------------------------------------

#define HH     8
#define MAX_B  64
#define MAX_T  2048
#define MAX_V  1000
#define CH     128
#define NPROJ  148

__device__ float g_hs[(size_t)MAX_B * MAX_T * HH];
__device__ int   g_progress[MAX_B];

__device__ __forceinline__ float fast_tanh(float x)
{
    float y;
    asm("tanh.approx.f32 %0, %1;" : "=f"(y) : "f"(x));
    return y;
}

__device__ __forceinline__ void store_release_gpu(int* p, int v)
{
    asm volatile("st.release.gpu.global.s32 [%0], %1;" :: "l"(p), "r"(v) : "memory");
}

__device__ __forceinline__ int load_acquire_gpu(const int* p)
{
    int v;
    asm volatile("ld.acquire.gpu.global.s32 %0, [%1];" : "=r"(v) : "l"(p) : "memory");
    return v;
}

__device__ __forceinline__ void store_cs(float* p, float4 v)
{
    asm volatile("st.global.cs.v4.f32 [%0], {%1,%2,%3,%4};"
                 :: "l"(p), "f"(v.x), "f"(v.y), "f"(v.z), "f"(v.w) : "memory");
}

__global__ void __launch_bounds__(256, 2)
rnn_fused_kernel(const void* __restrict__ Xv,
                 const void* __restrict__ lengthsv,
                 const float* __restrict__ emb,
                 const float* __restrict__ W_ih,
                 const float* __restrict__ W_hh,
                 const float* __restrict__ b_ih,
                 const float* __restrict__ b_hh,
                 const float* __restrict__ W_out,
                 const float* __restrict__ b_out,
                 float* __restrict__ out,
                 int B, int T, int V, int O, int tail)
{
    const int bid = blockIdx.x;
    const int tid = threadIdx.x;
    const int nchunk = (T + CH - 1) / CH;

    if (bid < B) {
        // =================== recurrence role ===================
        __shared__ float s_embproj[MAX_V * HH];   // 32 KB
        __shared__ int   s_tok[MAX_T + 2];        // 8 KB
        __shared__ int   s_is64;

        const int b = bid;

        {   // inline dtype detect: int64 tokens (<2^31) have zero odd words
            const int* x32 = (const int*)Xv;
            const int pairs = min(1024, (B * T) >> 1);
            int nz = 0;
            for (int i = tid; i < pairs; i += blockDim.x)
                nz |= (x32[2 * i + 1] != 0);
            const int any = __syncthreads_or(nz);
            if (tid == 0) s_is64 = !any;
            __syncthreads();
        }
        const int is64 = s_is64;

        if (is64) {
            const long long* X = (const long long*)Xv;
            for (int t = tid; t < T; t += blockDim.x) {
                int v = (int)X[(long long)b * T + t];
                s_tok[t] = min(max(v, 0), V - 1);
            }
        } else {
            const int* X = (const int*)Xv;
            for (int t = tid; t < T; t += blockDim.x) {
                int v = X[b * T + t];
                s_tok[t] = min(max(v, 0), V - 1);
            }
        }
        if (tid < 2) s_tok[T + tid] = 0;

        for (int v = tid; v < V; v += blockDim.x) {
            float e[HH];
#pragma unroll
            for (int h = 0; h < HH; h++) e[h] = emb[v * HH + h];
#pragma unroll
            for (int i = 0; i < HH; i++) {
                float s = b_ih[i] + b_hh[i];
#pragma unroll
                for (int h = 0; h < HH; h++)
                    s = fmaf(e[h], W_ih[i * HH + h], s);
                s_embproj[v * HH + i] = s;
            }
        }
        __syncthreads();

        if (tid >= 32) return;   // warp 0 only
        const int lane = tid;
        const int i    = lane & 7;

        float w0 = W_hh[i * HH + 0], w1 = W_hh[i * HH + 1];
        float w2 = W_hh[i * HH + 2], w3 = W_hh[i * HH + 3];
        float w4 = W_hh[i * HH + 4], w5 = W_hh[i * HH + 5];
        float w6 = W_hh[i * HH + 6], w7 = W_hh[i * HH + 7];

        float h0 = 0.f, h1 = 0.f, h2 = 0.f, h3 = 0.f;
        float h4 = 0.f, h5 = 0.f, h6 = 0.f, h7 = 0.f;

        float* __restrict__ hs_out = g_hs + (size_t)b * T * HH;

        int   tokB = s_tok[1];
        float xp   = s_embproj[s_tok[0] * HH + i];

        for (int c = 0; c < nchunk; c++) {
            const int tend = min(T, (c + 1) * CH);
#pragma unroll 4
            for (int t = c * CH; t < tend; t++) {
                const int   tokC = s_tok[t + 2];
                const float xp_n = s_embproj[tokB * HH + i];

                // two parallel 4-FFMA chains + join
                float a = fmaf(h0, w0, xp);
                a = fmaf(h1, w1, a);
                a = fmaf(h2, w2, a);
                a = fmaf(h3, w3, a);
                float bb = h4 * w4;
                bb = fmaf(h5, w5, bb);
                bb = fmaf(h6, w6, bb);
                bb = fmaf(h7, w7, bb);
                const float s = a + bb;

                const float y = fast_tanh(s);   // mask applied in proj role

                if (lane < HH) hs_out[t * HH + lane] = y;

                h0 = __shfl_sync(0xffffffffu, y, 0);
                h1 = __shfl_sync(0xffffffffu, y, 1);
                h2 = __shfl_sync(0xffffffffu, y, 2);
                h3 = __shfl_sync(0xffffffffu, y, 3);
                h4 = __shfl_sync(0xffffffffu, y, 4);
                h5 = __shfl_sync(0xffffffffu, y, 5);
                h6 = __shfl_sync(0xffffffffu, y, 6);
                h7 = __shfl_sync(0xffffffffu, y, 7);

                xp   = xp_n;
                tokB = tokC;
            }
            __syncwarp();                       // order all lanes' hs stores
            if (lane == 0) store_release_gpu(&g_progress[b], c + 1);
        }
        return;
    }

    // =================== projection role ===================
    const int p    = bid - B;
    const int nvec = O >> 2;                    // 250

    // lengths dtype: values >= 1, so int32 data has nonzero odd words
    const int* l32 = (const int*)lengthsv;
    int nzl = 0;
    for (int k = 1; k < B; k += 2) nzl |= (l32[k] != 0);
    const int is64l = !nzl;

    // tail passthrough (no hs dependency)
    if (p == 0 && tail > 0) {
        const long long base = (long long)B * T * O;
        if (tail == 2 * B) {
            if (tid < B) {
                long long lv = is64l ? ((const long long*)lengthsv)[tid]
                                     : (long long)l32[tid];
                ((long long*)(out + base))[tid] = lv;
            }
        } else {
            for (int k = tid; k < tail; k += 256) {
                float v = 0.0f;
                if (k < B)
                    v = (float)(is64l ? ((const long long*)lengthsv)[k]
                                      : (long long)l32[k]);
                out[base + k] = v;
            }
        }
    }

    // per-thread output weights (4 outputs x 8) + bias
    float w[4][HH];
    float4 bias = make_float4(0.f, 0.f, 0.f, 0.f);
    if (tid < nvec) {
#pragma unroll
        for (int k = 0; k < 4; k++) {
            const int o = tid * 4 + k;
#pragma unroll
            for (int h = 0; h < HH; h++)
                w[k][h] = W_out[o * HH + h];
        }
        bias = *(const float4*)(b_out + tid * 4);
    }

    const int ntiles = B * nchunk;

    // ---- phase 1: fully masked tiles (t0 >= len) — no dependency, run now ----
    for (int tile = p; tile < ntiles; tile += NPROJ) {
        const int c  = tile / B;
        const int b  = tile % B;
        const int t0 = c * CH;
        const int len = is64l ? (int)((const long long*)lengthsv)[b] : l32[b];
        if (len > t0) continue;                 // handled in phase 2

        if (tid < nvec) {
            const int rows = min(CH, T - t0);
            float* orow = out + ((size_t)b * T + t0) * O + tid * 4;
            for (int r = 0; r < rows; r++)
                store_cs(orow + (size_t)r * O, bias);
        }
    }

    // ---- phase 2: live tiles, in chunk order (matches production order) ----
    for (int tile = p; tile < ntiles; tile += NPROJ) {
        const int c  = tile / B;
        const int b  = tile % B;
        const int t0 = c * CH;
        const int len = is64l ? (int)((const long long*)lengthsv)[b] : l32[b];
        if (len <= t0) continue;                // done in phase 1

        if (tid == 0) {
            while (load_acquire_gpu(&g_progress[b]) <= c) __nanosleep(128);
        }
        __syncthreads();

        if (tid < nvec) {
            const int rows = min(CH, T - t0);
            const int rlim = min(rows, len - t0);   // >= 1 here
            const float* hsrow = g_hs + ((size_t)b * T + t0) * HH;
            float* orow = out + ((size_t)b * T + t0) * O + tid * 4;

            for (int r = 0; r < rlim; r++) {
                const float4 ha = __ldg((const float4*)(hsrow + (size_t)r * HH));
                const float4 hb = __ldg((const float4*)(hsrow + (size_t)r * HH) + 1);
                const float hh[HH] = {ha.x, ha.y, ha.z, ha.w, hb.x, hb.y, hb.z, hb.w};

                float a0 = bias.x, a1 = bias.y, a2 = bias.z, a3 = bias.w;
#pragma unroll
                for (int h = 0; h < HH; h++) {
                    a0 = fmaf(w[0][h], hh[h], a0);
                    a1 = fmaf(w[1][h], hh[h], a1);
                    a2 = fmaf(w[2][h], hh[h], a2);
                    a3 = fmaf(w[3][h], hh[h], a3);
                }
                float4 acc; acc.x = a0; acc.y = a1; acc.z = a2; acc.w = a3;
                store_cs(orow + (size_t)r * O, acc);
            }
            for (int r = rlim; r < rows; r++)       // masked remainder of tile
                store_cs(orow + (size_t)r * O, bias);
        }
    }
}

extern "C" void kernel_launch(void* const* d_in, const int* in_sizes, int n_in,
                              void* d_out, int out_size)
{
    const void*  X       = d_in[0];
    const void*  lengths = d_in[1];
    const float* emb     = (const float*)d_in[2];
    const float* W_ih    = (const float*)d_in[3];
    const float* W_hh    = (const float*)d_in[4];
    const float* b_ih    = (const float*)d_in[5];
    const float* b_hh    = (const float*)d_in[6];
    const float* W_out   = (const float*)d_in[7];
    const float* b_out   = (const float*)d_in[8];
    float*       out     = (float*)d_out;

    const int B  = in_sizes[1];
    const int BT = in_sizes[0];
    const int T  = BT / B;
    const int H  = in_sizes[5];
    const int V  = in_sizes[2] / H;
    const int O  = in_sizes[8];

    const long long tail = (long long)out_size - (long long)BT * O;

    void* progAddr = nullptr;
    cudaGetSymbolAddress(&progAddr, g_progress);
    cudaMemsetAsync(progAddr, 0, sizeof(int) * MAX_B);

    rnn_fused_kernel<<<B + NPROJ, 256>>>(X, lengths, emb, W_ih, W_hh, b_ih, b_hh,
                                         W_out, b_out, out,
                                         B, T, V, O, (int)(tail > 0 ? tail : 0));
}

// round 6
// speedup vs baseline: 2.1956x; 1.1286x over previous
#include <cuda_runtime.h>

// ---------------------------------------------------------------------------
// RNN_57208964382771: Elman RNN (tanh), B=64, T=2048, H=8, V=O=1000
// Fused persistent kernel, ONE BLOCK PER SM (grid = 148):
//   blocks [0, NREC)      : recurrence. 8 warps/block, one batch per warp.
//       lane i (mod 8) owns h_i; step = 2x4-FFMA chain + tanh.approx + 8 shfl
//       publish per CH=64 steps: syncwarp + threadfence + flag store
//   blocks [NREC, 148)    : projection over (chunk,batch) tiles, c-major.
//       masked rows (t >= len) stored immediately (bias only, no dependency)
//       live rows spin on progress flag (tid0, ld.acquire) then W_out·h+b_out
// Dedicated SMs for each role: proj traffic can no longer clog the
// recurrence SM's LSU/MIO queues.
// ---------------------------------------------------------------------------

#define HH     8
#define MAX_B  64
#define MAX_T  2048
#define MAX_V  1000
#define CH     64
#define WPB    8            // recurrence warps (batches) per block
#define GRID   148

__device__ float g_hs[(size_t)MAX_B * MAX_T * HH];
__device__ int   g_progress[MAX_B];

__device__ __forceinline__ float fast_tanh(float x)
{
    float y;
    asm("tanh.approx.f32 %0, %1;" : "=f"(y) : "f"(x));
    return y;
}

__device__ __forceinline__ int load_acquire_gpu(const int* p)
{
    int v;
    asm volatile("ld.acquire.gpu.global.s32 %0, [%1];" : "=r"(v) : "l"(p) : "memory");
    return v;
}

__device__ __forceinline__ void store_cs(float* p, float4 v)
{
    asm volatile("st.global.cs.v4.f32 [%0], {%1,%2,%3,%4};"
                 :: "l"(p), "f"(v.x), "f"(v.y), "f"(v.z), "f"(v.w) : "memory");
}

extern __shared__ char dsmem[];

__global__ void __launch_bounds__(256, 1)
rnn_fused_kernel(const void* __restrict__ Xv,
                 const void* __restrict__ lengthsv,
                 const float* __restrict__ emb,
                 const float* __restrict__ W_ih,
                 const float* __restrict__ W_hh,
                 const float* __restrict__ b_ih,
                 const float* __restrict__ b_hh,
                 const float* __restrict__ W_out,
                 const float* __restrict__ b_out,
                 float* __restrict__ out,
                 int B, int T, int V, int O, int tail, int nrec)
{
    const int bid = blockIdx.x;
    const int tid = threadIdx.x;
    const int nchunk = (T + CH - 1) / CH;

    if (bid < nrec) {
        // =================== recurrence role ===================
        float* s_embproj = (float*)dsmem;                   // V*HH floats
        int*   s_tok     = (int*)(dsmem + MAX_V * HH * 4);  // WPB*(T+2) ints
        __shared__ int s_is64;

        {   // inline dtype detect on X: int64 (<2^31) => odd words all zero
            const int* x32 = (const int*)Xv;
            const int pairs = min(1024, (B * T) >> 1);
            int nz = 0;
            for (int i = tid; i < pairs; i += blockDim.x)
                nz |= (x32[2 * i + 1] != 0);
            const int any = __syncthreads_or(nz);
            if (tid == 0) s_is64 = !any;
            __syncthreads();
        }
        const int is64 = s_is64;

        // --- tokens for this block's WPB batches ---
        const int b0     = bid * WPB;
        const int nbatch = min(WPB, B - b0);
        const int TOT    = nbatch * T;
        if (is64) {
            const long long* X = (const long long*)Xv;
            for (int k = tid; k < TOT; k += blockDim.x) {
                const int wq = k / T, t = k - wq * T;
                int v = (int)X[(long long)(b0 + wq) * T + t];
                s_tok[wq * (T + 2) + t] = min(max(v, 0), V - 1);
            }
        } else {
            const int* X = (const int*)Xv;
            for (int k = tid; k < TOT; k += blockDim.x) {
                const int wq = k / T, t = k - wq * T;
                int v = X[(b0 + wq) * T + t];
                s_tok[wq * (T + 2) + t] = min(max(v, 0), V - 1);
            }
        }
        if (tid < 2 * WPB) s_tok[(tid >> 1) * (T + 2) + T + (tid & 1)] = 0;

        // --- embedding projection with both biases folded in ---
        for (int v = tid; v < V; v += blockDim.x) {
            float e[HH];
#pragma unroll
            for (int h = 0; h < HH; h++) e[h] = emb[v * HH + h];
#pragma unroll
            for (int i = 0; i < HH; i++) {
                float s = b_ih[i] + b_hh[i];
#pragma unroll
                for (int h = 0; h < HH; h++)
                    s = fmaf(e[h], W_ih[i * HH + h], s);
                s_embproj[v * HH + i] = s;
            }
        }
        __syncthreads();

        const int wq    = tid >> 5;
        const int batch = b0 + wq;
        if (batch >= B) return;
        const int lane = tid & 31;
        const int i    = lane & 7;            // lanes 8-31 shadow 0-7

        const float w0 = W_hh[i * HH + 0], w1 = W_hh[i * HH + 1];
        const float w2 = W_hh[i * HH + 2], w3 = W_hh[i * HH + 3];
        const float w4 = W_hh[i * HH + 4], w5 = W_hh[i * HH + 5];
        const float w6 = W_hh[i * HH + 6], w7 = W_hh[i * HH + 7];

        float h0 = 0.f, h1 = 0.f, h2 = 0.f, h3 = 0.f;
        float h4 = 0.f, h5 = 0.f, h6 = 0.f, h7 = 0.f;

        float* __restrict__ hs_out = g_hs + (size_t)batch * T * HH;
        const int* __restrict__ tok = s_tok + wq * (T + 2);

        int   tokB = tok[1];
        float xp   = s_embproj[tok[0] * HH + i];

        for (int c = 0; c < nchunk; c++) {
            const int t0 = c * CH;
            const int full = (t0 + CH <= T);
            if (full) {
#pragma unroll
                for (int tt = 0; tt < CH; tt++) {
                    const int   t    = t0 + tt;
                    const int   tokC = tok[t + 2];
                    const float xp_n = s_embproj[tokB * HH + i];

                    float a = fmaf(h0, w0, xp);
                    a = fmaf(h1, w1, a);
                    a = fmaf(h2, w2, a);
                    a = fmaf(h3, w3, a);
                    float bb = h4 * w4;
                    bb = fmaf(h5, w5, bb);
                    bb = fmaf(h6, w6, bb);
                    bb = fmaf(h7, w7, bb);

                    const float y = fast_tanh(a + bb);
                    if (lane < HH) hs_out[t * HH + lane] = y;

                    h0 = __shfl_sync(0xffffffffu, y, 0);
                    h1 = __shfl_sync(0xffffffffu, y, 1);
                    h2 = __shfl_sync(0xffffffffu, y, 2);
                    h3 = __shfl_sync(0xffffffffu, y, 3);
                    h4 = __shfl_sync(0xffffffffu, y, 4);
                    h5 = __shfl_sync(0xffffffffu, y, 5);
                    h6 = __shfl_sync(0xffffffffu, y, 6);
                    h7 = __shfl_sync(0xffffffffu, y, 7);

                    xp   = xp_n;
                    tokB = tokC;
                }
            } else {
                const int tend = min(T, t0 + CH);
                for (int t = t0; t < tend; t++) {
                    const int   tokC = tok[t + 2];
                    const float xp_n = s_embproj[tokB * HH + i];
                    float a = fmaf(h0, w0, xp);
                    a = fmaf(h1, w1, a);
                    a = fmaf(h2, w2, a);
                    a = fmaf(h3, w3, a);
                    float bb = h4 * w4;
                    bb = fmaf(h5, w5, bb);
                    bb = fmaf(h6, w6, bb);
                    bb = fmaf(h7, w7, bb);
                    const float y = fast_tanh(a + bb);
                    if (lane < HH) hs_out[t * HH + lane] = y;
                    h0 = __shfl_sync(0xffffffffu, y, 0);
                    h1 = __shfl_sync(0xffffffffu, y, 1);
                    h2 = __shfl_sync(0xffffffffu, y, 2);
                    h3 = __shfl_sync(0xffffffffu, y, 3);
                    h4 = __shfl_sync(0xffffffffu, y, 4);
                    h5 = __shfl_sync(0xffffffffu, y, 5);
                    h6 = __shfl_sync(0xffffffffu, y, 6);
                    h7 = __shfl_sync(0xffffffffu, y, 7);
                    xp   = xp_n;
                    tokB = tokC;
                }
            }
            __syncwarp();
            if (lane == 0) {
                __threadfence();
                *(volatile int*)&g_progress[batch] = c + 1;
            }
        }
        return;
    }

    // =================== projection role ===================
    const int p    = bid - nrec;
    const int NPROJ = GRID - nrec;
    const int nvec = O >> 2;                    // 250

    // lengths dtype: values >= 1, so int32 data has nonzero odd words
    const int* l32 = (const int*)lengthsv;
    int nzl = 0;
    for (int k = 1; k < B; k += 2) nzl |= (l32[k] != 0);
    const int is64l = !nzl;

    if (p == 0 && tail > 0) {
        const long long base = (long long)B * T * O;
        if (tail == 2 * B) {
            if (tid < B) {
                long long lv = is64l ? ((const long long*)lengthsv)[tid]
                                     : (long long)l32[tid];
                ((long long*)(out + base))[tid] = lv;
            }
        } else {
            for (int k = tid; k < tail; k += 256) {
                float v = 0.0f;
                if (k < B)
                    v = (float)(is64l ? ((const long long*)lengthsv)[k]
                                      : (long long)l32[k]);
                out[base + k] = v;
            }
        }
    }

    float w[4][HH];
    float4 bias = make_float4(0.f, 0.f, 0.f, 0.f);
    if (tid < nvec) {
#pragma unroll
        for (int k = 0; k < 4; k++) {
            const int o = tid * 4 + k;
#pragma unroll
            for (int h = 0; h < HH; h++)
                w[k][h] = W_out[o * HH + h];
        }
        bias = *(const float4*)(b_out + tid * 4);
    }

    const int ntiles = B * nchunk;

    // ---- phase 1: fully masked tiles — no dependency, run immediately ----
    for (int tile = p; tile < ntiles; tile += NPROJ) {
        const int c  = tile / B;
        const int b  = tile % B;
        const int t0 = c * CH;
        const int len = is64l ? (int)((const long long*)lengthsv)[b] : l32[b];
        if (len > t0) continue;
        if (tid < nvec) {
            const int rows = min(CH, T - t0);
            float* orow = out + ((size_t)b * T + t0) * O + tid * 4;
            for (int r = 0; r < rows; r++)
                store_cs(orow + (size_t)r * O, bias);
        }
    }

    // ---- phase 2: live tiles, chunk-major (matches production order) ----
    for (int tile = p; tile < ntiles; tile += NPROJ) {
        const int c  = tile / B;
        const int b  = tile % B;
        const int t0 = c * CH;
        const int len = is64l ? (int)((const long long*)lengthsv)[b] : l32[b];
        if (len <= t0) continue;

        if (tid == 0) {
            while (load_acquire_gpu(&g_progress[b]) <= c) __nanosleep(64);
        }
        __syncthreads();

        if (tid < nvec) {
            const int rows = min(CH, T - t0);
            const int rlim = min(rows, len - t0);
            const float* hsrow = g_hs + ((size_t)b * T + t0) * HH;
            float* orow = out + ((size_t)b * T + t0) * O + tid * 4;

            for (int r = 0; r < rlim; r++) {
                const float4 ha = __ldg((const float4*)(hsrow + (size_t)r * HH));
                const float4 hb = __ldg((const float4*)(hsrow + (size_t)r * HH) + 1);
                const float hh[HH] = {ha.x, ha.y, ha.z, ha.w, hb.x, hb.y, hb.z, hb.w};

                float a0 = bias.x, a1 = bias.y, a2 = bias.z, a3 = bias.w;
#pragma unroll
                for (int h = 0; h < HH; h++) {
                    a0 = fmaf(w[0][h], hh[h], a0);
                    a1 = fmaf(w[1][h], hh[h], a1);
                    a2 = fmaf(w[2][h], hh[h], a2);
                    a3 = fmaf(w[3][h], hh[h], a3);
                }
                float4 acc; acc.x = a0; acc.y = a1; acc.z = a2; acc.w = a3;
                store_cs(orow + (size_t)r * O, acc);
            }
            for (int r = rlim; r < rows; r++)
                store_cs(orow + (size_t)r * O, bias);
        }
    }
}

extern "C" void kernel_launch(void* const* d_in, const int* in_sizes, int n_in,
                              void* d_out, int out_size)
{
    const void*  X       = d_in[0];
    const void*  lengths = d_in[1];
    const float* emb     = (const float*)d_in[2];
    const float* W_ih    = (const float*)d_in[3];
    const float* W_hh    = (const float*)d_in[4];
    const float* b_ih    = (const float*)d_in[5];
    const float* b_hh    = (const float*)d_in[6];
    const float* W_out   = (const float*)d_in[7];
    const float* b_out   = (const float*)d_in[8];
    float*       out     = (float*)d_out;

    const int B  = in_sizes[1];
    const int BT = in_sizes[0];
    const int T  = BT / B;
    const int H  = in_sizes[5];
    const int V  = in_sizes[2] / H;
    const int O  = in_sizes[8];

    const long long tail = (long long)out_size - (long long)BT * O;
    const int nrec = (B + WPB - 1) / WPB;          // 8 for B=64

    const int smemBytes = MAX_V * HH * 4 + WPB * (T + 2) * 4;   // ~98 KB
    static int attrDone = 0;
    if (!attrDone) {
        cudaFuncSetAttribute(rnn_fused_kernel,
                             cudaFuncAttributeMaxDynamicSharedMemorySize,
                             smemBytes);
        attrDone = 1;
    }

    void* progAddr = nullptr;
    cudaGetSymbolAddress(&progAddr, g_progress);
    cudaMemsetAsync(progAddr, 0, sizeof(int) * MAX_B);

    rnn_fused_kernel<<<GRID, 256, smemBytes>>>(X, lengths, emb, W_ih, W_hh,
                                               b_ih, b_hh, W_out, b_out, out,
                                               B, T, V, O,
                                               (int)(tail > 0 ? tail : 0), nrec);
}

// round 8
// speedup vs baseline: 2.4807x; 1.1299x over previous
#include <cuda_runtime.h>

// ---------------------------------------------------------------------------
// RNN_57208964382771: Elman RNN (tanh), B=64, T=2048, H=8, V=O=1000
// Fused persistent kernel, ONE BLOCK PER SM (grid = 148):
//   blocks [0, 16)     : recurrence. 4 live warps/block => ONE warp per SMSP.
//                        (R7 bug: warps 4-7 of 256-thread block fell through
//                         into the recurrence with uninitialized s_tok ->
//                         OOB shared read. Now hard-gated: tid >= WPB*32.)
//   blocks [16, 148)   : projection over (chunk,batch) tiles, c-major.
//       masked rows (t >= len) stored immediately (bias only)
//       live rows spin on progress flag (tid0, ld.acquire) then W_out·h+b_out
// ---------------------------------------------------------------------------

#define HH     8
#define MAX_B  64
#define MAX_T  2048
#define MAX_V  1000
#define CH     64
#define WPB    4            // recurrence warps per block -> 1 per SMSP
#define GRID   148

__device__ float g_hs[(size_t)MAX_B * MAX_T * HH];
__device__ int   g_progress[MAX_B];

__device__ __forceinline__ float fast_tanh(float x)
{
    float y;
    asm("tanh.approx.f32 %0, %1;" : "=f"(y) : "f"(x));
    return y;
}

__device__ __forceinline__ int load_acquire_gpu(const int* p)
{
    int v;
    asm volatile("ld.acquire.gpu.global.s32 %0, [%1];" : "=r"(v) : "l"(p) : "memory");
    return v;
}

__device__ __forceinline__ void store_cs(float* p, float4 v)
{
    asm volatile("st.global.cs.v4.f32 [%0], {%1,%2,%3,%4};"
                 :: "l"(p), "f"(v.x), "f"(v.y), "f"(v.z), "f"(v.w) : "memory");
}

extern __shared__ char dsmem[];

__global__ void __launch_bounds__(256, 1)
rnn_fused_kernel(const void* __restrict__ Xv,
                 const void* __restrict__ lengthsv,
                 const float* __restrict__ emb,
                 const float* __restrict__ W_ih,
                 const float* __restrict__ W_hh,
                 const float* __restrict__ b_ih,
                 const float* __restrict__ b_hh,
                 const float* __restrict__ W_out,
                 const float* __restrict__ b_out,
                 float* __restrict__ out,
                 int B, int T, int V, int O, int tail, int nrec)
{
    const int bid = blockIdx.x;
    const int tid = threadIdx.x;
    const int nchunk = (T + CH - 1) / CH;

    if (bid < nrec) {
        // =================== recurrence role ===================
        float* s_embproj = (float*)dsmem;                   // V*HH floats
        int*   s_tok     = (int*)(dsmem + MAX_V * HH * 4);  // WPB*(T+2) ints
        __shared__ int s_is64;

        {   // inline dtype detect on X: int64 (<2^31) => odd words all zero
            const int* x32 = (const int*)Xv;
            const int pairs = min(1024, (B * T) >> 1);
            int nz = 0;
            for (int i = tid; i < pairs; i += blockDim.x)
                nz |= (x32[2 * i + 1] != 0);
            const int any = __syncthreads_or(nz);
            if (tid == 0) s_is64 = !any;
            __syncthreads();
        }
        const int is64 = s_is64;

        // --- tokens for this block's WPB batches (all 256 threads help) ---
        const int b0     = bid * WPB;
        const int nbatch = min(WPB, B - b0);
        const int TOT    = nbatch * T;
        if (is64) {
            const long long* X = (const long long*)Xv;
            for (int k = tid; k < TOT; k += blockDim.x) {
                const int wq = k / T, t = k - wq * T;
                int v = (int)X[(long long)(b0 + wq) * T + t];
                s_tok[wq * (T + 2) + t] = min(max(v, 0), V - 1);
            }
        } else {
            const int* X = (const int*)Xv;
            for (int k = tid; k < TOT; k += blockDim.x) {
                const int wq = k / T, t = k - wq * T;
                int v = X[(b0 + wq) * T + t];
                s_tok[wq * (T + 2) + t] = min(max(v, 0), V - 1);
            }
        }
        if (tid < 2 * WPB) s_tok[(tid >> 1) * (T + 2) + T + (tid & 1)] = 0;

        // --- embedding projection with both biases folded in ---
        for (int v = tid; v < V; v += blockDim.x) {
            float e[HH];
#pragma unroll
            for (int h = 0; h < HH; h++) e[h] = emb[v * HH + h];
#pragma unroll
            for (int i = 0; i < HH; i++) {
                float s = b_ih[i] + b_hh[i];
#pragma unroll
                for (int h = 0; h < HH; h++)
                    s = fmaf(e[h], W_ih[i * HH + h], s);
                s_embproj[v * HH + i] = s;
            }
        }
        __syncthreads();

        // ---- ONLY the first WPB warps run the recurrence (R7 fix) ----
        if (tid >= WPB * 32) return;
        const int wq    = tid >> 5;
        const int batch = b0 + wq;
        if (batch >= B) return;
        const int lane = tid & 31;
        const int i    = lane & 7;            // lanes 8-31 shadow 0-7

        const float w0 = W_hh[i * HH + 0], w1 = W_hh[i * HH + 1];
        const float w2 = W_hh[i * HH + 2], w3 = W_hh[i * HH + 3];
        const float w4 = W_hh[i * HH + 4], w5 = W_hh[i * HH + 5];
        const float w6 = W_hh[i * HH + 6], w7 = W_hh[i * HH + 7];

        float h0 = 0.f, h1 = 0.f, h2 = 0.f, h3 = 0.f;
        float h4 = 0.f, h5 = 0.f, h6 = 0.f, h7 = 0.f;

        float* __restrict__ hs_out = g_hs + (size_t)batch * T * HH;
        const int* __restrict__ tok = s_tok + wq * (T + 2);

        int   tokB = tok[1];
        float xp   = s_embproj[tok[0] * HH + i];

        for (int c = 0; c < nchunk; c++) {
            const int t0 = c * CH;
            const int full = (t0 + CH <= T);
            if (full) {
#pragma unroll
                for (int tt = 0; tt < CH; tt++) {
                    const int   t    = t0 + tt;
                    const int   tokC = tok[t + 2];
                    const float xp_n = s_embproj[tokB * HH + i];

                    float a = fmaf(h0, w0, xp);
                    a = fmaf(h1, w1, a);
                    a = fmaf(h2, w2, a);
                    a = fmaf(h3, w3, a);
                    float bb = h4 * w4;
                    bb = fmaf(h5, w5, bb);
                    bb = fmaf(h6, w6, bb);
                    bb = fmaf(h7, w7, bb);

                    const float y = fast_tanh(a + bb);
                    if (lane < HH) hs_out[t * HH + lane] = y;

                    h0 = __shfl_sync(0xffffffffu, y, 0);
                    h1 = __shfl_sync(0xffffffffu, y, 1);
                    h2 = __shfl_sync(0xffffffffu, y, 2);
                    h3 = __shfl_sync(0xffffffffu, y, 3);
                    h4 = __shfl_sync(0xffffffffu, y, 4);
                    h5 = __shfl_sync(0xffffffffu, y, 5);
                    h6 = __shfl_sync(0xffffffffu, y, 6);
                    h7 = __shfl_sync(0xffffffffu, y, 7);

                    xp   = xp_n;
                    tokB = tokC;
                }
            } else {
                const int tend = min(T, t0 + CH);
                for (int t = t0; t < tend; t++) {
                    const int   tokC = tok[t + 2];
                    const float xp_n = s_embproj[tokB * HH + i];
                    float a = fmaf(h0, w0, xp);
                    a = fmaf(h1, w1, a);
                    a = fmaf(h2, w2, a);
                    a = fmaf(h3, w3, a);
                    float bb = h4 * w4;
                    bb = fmaf(h5, w5, bb);
                    bb = fmaf(h6, w6, bb);
                    bb = fmaf(h7, w7, bb);
                    const float y = fast_tanh(a + bb);
                    if (lane < HH) hs_out[t * HH + lane] = y;
                    h0 = __shfl_sync(0xffffffffu, y, 0);
                    h1 = __shfl_sync(0xffffffffu, y, 1);
                    h2 = __shfl_sync(0xffffffffu, y, 2);
                    h3 = __shfl_sync(0xffffffffu, y, 3);
                    h4 = __shfl_sync(0xffffffffu, y, 4);
                    h5 = __shfl_sync(0xffffffffu, y, 5);
                    h6 = __shfl_sync(0xffffffffu, y, 6);
                    h7 = __shfl_sync(0xffffffffu, y, 7);
                    xp   = xp_n;
                    tokB = tokC;
                }
            }
            __syncwarp();
            if (lane == 0) {
                __threadfence();
                *(volatile int*)&g_progress[batch] = c + 1;
            }
        }
        return;
    }

    // =================== projection role ===================
    const int p     = bid - nrec;
    const int NPROJ = GRID - nrec;
    const int nvec  = O >> 2;                   // 250

    // lengths dtype: values >= 1, so int32 data has nonzero odd words
    const int* l32 = (const int*)lengthsv;
    int nzl = 0;
    for (int k = 1; k < B; k += 2) nzl |= (l32[k] != 0);
    const int is64l = !nzl;

    if (p == 0 && tail > 0) {
        const long long base = (long long)B * T * O;
        if (tail == 2 * B) {
            if (tid < B) {
                long long lv = is64l ? ((const long long*)lengthsv)[tid]
                                     : (long long)l32[tid];
                ((long long*)(out + base))[tid] = lv;
            }
        } else {
            for (int k = tid; k < tail; k += 256) {
                float v = 0.0f;
                if (k < B)
                    v = (float)(is64l ? ((const long long*)lengthsv)[k]
                                      : (long long)l32[k]);
                out[base + k] = v;
            }
        }
    }

    float w[4][HH];
    float4 bias = make_float4(0.f, 0.f, 0.f, 0.f);
    if (tid < nvec) {
#pragma unroll
        for (int k = 0; k < 4; k++) {
            const int o = tid * 4 + k;
#pragma unroll
            for (int h = 0; h < HH; h++)
                w[k][h] = W_out[o * HH + h];
        }
        bias = *(const float4*)(b_out + tid * 4);
    }

    const int ntiles = B * nchunk;

    // ---- phase 1: fully masked tiles — no dependency, run immediately ----
    for (int tile = p; tile < ntiles; tile += NPROJ) {
        const int c  = tile / B;
        const int b  = tile % B;
        const int t0 = c * CH;
        const int len = is64l ? (int)((const long long*)lengthsv)[b] : l32[b];
        if (len > t0) continue;
        if (tid < nvec) {
            const int rows = min(CH, T - t0);
            float* orow = out + ((size_t)b * T + t0) * O + tid * 4;
            for (int r = 0; r < rows; r++)
                store_cs(orow + (size_t)r * O, bias);
        }
    }

    // ---- phase 2: live tiles, chunk-major (matches production order) ----
    for (int tile = p; tile < ntiles; tile += NPROJ) {
        const int c  = tile / B;
        const int b  = tile % B;
        const int t0 = c * CH;
        const int len = is64l ? (int)((const long long*)lengthsv)[b] : l32[b];
        if (len <= t0) continue;

        if (tid == 0) {
            while (load_acquire_gpu(&g_progress[b]) <= c) __nanosleep(64);
        }
        __syncthreads();

        if (tid < nvec) {
            const int rows = min(CH, T - t0);
            const int rlim = min(rows, len - t0);
            const float* hsrow = g_hs + ((size_t)b * T + t0) * HH;
            float* orow = out + ((size_t)b * T + t0) * O + tid * 4;

            for (int r = 0; r < rlim; r++) {
                const float4 ha = __ldg((const float4*)(hsrow + (size_t)r * HH));
                const float4 hb = __ldg((const float4*)(hsrow + (size_t)r * HH) + 1);
                const float hh[HH] = {ha.x, ha.y, ha.z, ha.w, hb.x, hb.y, hb.z, hb.w};

                float a0 = bias.x, a1 = bias.y, a2 = bias.z, a3 = bias.w;
#pragma unroll
                for (int h = 0; h < HH; h++) {
                    a0 = fmaf(w[0][h], hh[h], a0);
                    a1 = fmaf(w[1][h], hh[h], a1);
                    a2 = fmaf(w[2][h], hh[h], a2);
                    a3 = fmaf(w[3][h], hh[h], a3);
                }
                float4 acc; acc.x = a0; acc.y = a1; acc.z = a2; acc.w = a3;
                store_cs(orow + (size_t)r * O, acc);
            }
            for (int r = rlim; r < rows; r++)
                store_cs(orow + (size_t)r * O, bias);
        }
    }
}

extern "C" void kernel_launch(void* const* d_in, const int* in_sizes, int n_in,
                              void* d_out, int out_size)
{
    const void*  X       = d_in[0];
    const void*  lengths = d_in[1];
    const float* emb     = (const float*)d_in[2];
    const float* W_ih    = (const float*)d_in[3];
    const float* W_hh    = (const float*)d_in[4];
    const float* b_ih    = (const float*)d_in[5];
    const float* b_hh    = (const float*)d_in[6];
    const float* W_out   = (const float*)d_in[7];
    const float* b_out   = (const float*)d_in[8];
    float*       out     = (float*)d_out;

    const int B  = in_sizes[1];
    const int BT = in_sizes[0];
    const int T  = BT / B;
    const int H  = in_sizes[5];
    const int V  = in_sizes[2] / H;
    const int O  = in_sizes[8];

    const long long tail = (long long)out_size - (long long)BT * O;
    const int nrec = (B + WPB - 1) / WPB;          // 16 for B=64

    const int smemBytes = MAX_V * HH * 4 + WPB * (T + 2) * 4;   // ~65 KB
    cudaFuncSetAttribute(rnn_fused_kernel,
                         cudaFuncAttributeMaxDynamicSharedMemorySize,
                         smemBytes);

    void* progAddr = nullptr;
    cudaGetSymbolAddress(&progAddr, g_progress);
    cudaMemsetAsync(progAddr, 0, sizeof(int) * MAX_B);

    rnn_fused_kernel<<<GRID, 256, smemBytes>>>(X, lengths, emb, W_ih, W_hh,
                                               b_ih, b_hh, W_out, b_out, out,
                                               B, T, V, O,
                                               (int)(tail > 0 ? tail : 0), nrec);
}